// round 9
// baseline (speedup 1.0000x reference)
#include <cuda_runtime.h>

#define FULLMASK 0xffffffffu

// Two rows per warp: lanes 0-15 / 16-31 are independent 16-lane groups.
// All shuffles use width=16 so the halves never interact.

__device__ __forceinline__ float max16(float v) {
#pragma unroll
  for (int m = 8; m; m >>= 1) v = fmaxf(v, __shfl_xor_sync(FULLMASK, v, m, 16));
  return v;
}

__device__ __forceinline__ float sum16(float v) {
#pragma unroll
  for (int m = 8; m; m >>= 1) v += __shfl_xor_sync(FULLMASK, v, m, 16);
  return v;
}

// Load one 256-float byte-distribution vector (16 rows x 16 cols, row-major).
// Lane l holds row l.  hs = row-l sum (lane-local).  ls = col-l sum via
// butterfly reduce-scatter (15 shfl; optimal for this pattern).
__device__ __forceinline__ void load_sums(const float* __restrict__ p, int l,
                                          float& hs, float& ls) {
  const float4* p4 = reinterpret_cast<const float4*>(p) + 4 * l;
  float4 x0 = p4[0], x1 = p4[1], x2 = p4[2], x3 = p4[3];
  float u[16] = {x0.x, x0.y, x0.z, x0.w, x1.x, x1.y, x1.z, x1.w,
                 x2.x, x2.y, x2.z, x2.w, x3.x, x3.y, x3.z, x3.w};
  hs = ((u[0] + u[1]) + (u[2] + u[3])) + ((u[4] + u[5]) + (u[6] + u[7])) +
       ((u[8] + u[9]) + (u[10] + u[11])) + ((u[12] + u[13]) + (u[14] + u[15]));

  bool b8 = (l & 8) != 0;
  float w[8];
#pragma unroll
  for (int k = 0; k < 8; k++) {
    float send = b8 ? u[k] : u[k + 8];
    float keep = b8 ? u[k + 8] : u[k];
    w[k] = keep + __shfl_xor_sync(FULLMASK, send, 8, 16);
  }
  bool b4 = (l & 4) != 0;
  float x[4];
#pragma unroll
  for (int k = 0; k < 4; k++) {
    float send = b4 ? w[k] : w[k + 4];
    float keep = b4 ? w[k + 4] : w[k];
    x[k] = keep + __shfl_xor_sync(FULLMASK, send, 4, 16);
  }
  bool b2 = (l & 2) != 0;
  float y[2];
#pragma unroll
  for (int k = 0; k < 2; k++) {
    float send = b2 ? x[k] : x[k + 2];
    float keep = b2 ? x[k + 2] : x[k];
    y[k] = keep + __shfl_xor_sync(FULLMASK, send, 2, 16);
  }
  bool b1 = (l & 1) != 0;
  float send = b1 ? y[0] : y[1];
  float keep = b1 ? y[1] : y[0];
  ls = keep + __shfl_xor_sync(FULLMASK, send, 1, 16);
}

// Conv via smem gathers (bex/bey hold the 16 softmax numerators of this
// half-warp's group, already stored and __syncwarp'ed by the caller):
//   ex_all: 4x LDS.128 broadcast (same address within the 16-lane group)
//   ey rotated: 16x conflict-free LDS.32 (per-lane permutation of 16 banks)
//   qs = cyclic conv (lane-local FMA), split qlo/qhi for the carry outputs
//   Zx, Zy lane-local (rotation preserves the sum) -> no sum16 for Z.
__device__ __forceinline__ void conv_smem(const float* __restrict__ bex,
                                          const float* __restrict__ bey, int l,
                                          float& s0, float& s1,
                                          float& C0, float& C1) {
  const float4* e4 = reinterpret_cast<const float4*>(bex);
  float4 a0 = e4[0], a1 = e4[1], a2 = e4[2], a3 = e4[3];
  float exall[16] = {a0.x, a0.y, a0.z, a0.w, a1.x, a1.y, a1.z, a1.w,
                     a2.x, a2.y, a2.z, a2.w, a3.x, a3.y, a3.z, a3.w};
  float Zx = ((exall[0] + exall[1]) + (exall[2] + exall[3])) +
             ((exall[4] + exall[5]) + (exall[6] + exall[7])) +
             ((exall[8] + exall[9]) + (exall[10] + exall[11])) +
             ((exall[12] + exall[13]) + (exall[14] + exall[15]));

  float qlo = 0.f, qhi = 0.f, Zy = 0.f;
#pragma unroll
  for (int A = 0; A < 16; A++) {
    float r = bey[(l - A) & 15];   // ey[(l-A) mod 16], conflict-free LDS.32
    Zy += r;
    if (A <= l) qlo = fmaf(exall[A], r, qlo);
    else        qhi = fmaf(exall[A], r, qhi);
  }
  float inv = 1.0f / (Zx * Zy);
  float qs  = qlo + qhi;
  s0 = qs * inv;
  s1 = __shfl_sync(FULLMASK, qs, (l + 15) & 15, 16) * inv;
  C0 = sum16(qhi) * inv;
  C1 = fmaf(__shfl_sync(FULLMASK, qlo, 15, 16), inv, C0);
}

__global__ __launch_bounds__(256, 4) void neural_alu_kernel(
    const float* __restrict__ A, const float* __restrict__ B,
    float* __restrict__ O, int nrows) {
  // Per-warp scratch: 5 buffers (exl, eyl, exh, eyh, el) x 2 halves x 16.
  __shared__ float sbuf[8][5][32];

  int tid  = threadIdx.x;
  int warp = tid >> 5;
  int half = (tid >> 4) & 1;
  int l    = tid & 15;
  int gid  = blockIdx.x * blockDim.x + tid;
  int row  = gid >> 4;
  if (row >= nrows) return;

  float* bexl = &sbuf[warp][0][half * 16];
  float* beyl = &sbuf[warp][1][half * 16];
  float* bexh = &sbuf[warp][2][half * 16];
  float* beyh = &sbuf[warp][3][half * 16];
  float* bel  = &sbuf[warp][4][half * 16];

  const float* a = A + (size_t)row * 1024;
  const float* b = B + (size_t)row * 1024;
  float*       o = O + (size_t)row * 1024;

  float u1 = 0.f;  // P(carry=1); initial one-hot carry_zero -> 0 exactly

#pragma unroll
  for (int i = 0; i < 4; i++) {
    // WAR guard: previous byte's smem reads must finish before we overwrite.
    __syncwarp();

    float ah, al, bh, bl;
    load_sums(a + i * 256, l, ah, al);
    load_sums(b + i * 256, l, bh, bl);

    // Softmax numerators (per-lane), then publish to smem for the gathers.
    float exl = __expf(100.f * (al - max16(al)));
    float eyl = __expf(100.f * (bl - max16(bl)));
    float exh = __expf(100.f * (ah - max16(ah)));
    float eyh = __expf(100.f * (bh - max16(bh)));
    bexl[l] = exl; beyl[l] = eyl; bexh[l] = exh; beyh[l] = eyh;
    __syncwarp();

    float s0l, s1l, c0l, c1l, s0h, s1h, c0h, c1h;
    conv_smem(bexl, beyl, l, s0l, s1l, c0l, c1l);
    conv_smem(bexh, beyh, l, s0h, s1h, c0h, c1h);

    // Carry chain: pc = sigmoid(100*(u1-u0)); exp(+100)=inf -> pc=0 exactly.
    float pcl = 1.f / (1.f + __expf(fmaf(-200.f, u1, 100.f)));
    u1 = fmaf(c1l - c0l, pcl, c0l);
    float pch = 1.f / (1.f + __expf(fmaf(-200.f, u1, 100.f)));
    u1 = fmaf(c1h - c0h, pch, c0h);

    float sl = fmaf(s1l - s0l, pcl, s0l);
    float sh = fmaf(s1h - s0h, pch, s0h);

    // _n2b = outer product of two 16-softmaxes. s in [0,1] -> fixed -50 shift.
    float el = __expf(fmaf(100.f, sl, -50.f));
    float eh = __expf(fmaf(100.f, sh, -50.f));

    bel[l] = el;
    float invZh = 1.0f / sum16(eh);   // overlaps the smem publish
    __syncwarp();

    const float4* el4 = reinterpret_cast<const float4*>(bel);
    float4 e0 = el4[0], e1 = el4[1], e2 = el4[2], e3 = el4[3];
    float Zl = ((e0.x + e0.y) + (e0.z + e0.w)) + ((e1.x + e1.y) + (e1.z + e1.w)) +
               ((e2.x + e2.y) + (e2.z + e2.w)) + ((e3.x + e3.y) + (e3.z + e3.w));
    float scale = (eh * invZh) / Zl;  // eh/(Zh*Zl), grouped vs overflow

    float4* op = reinterpret_cast<float4*>(o + i * 256) + 4 * l;
    op[0] = make_float4(scale * e0.x, scale * e0.y, scale * e0.z, scale * e0.w);
    op[1] = make_float4(scale * e1.x, scale * e1.y, scale * e1.z, scale * e1.w);
    op[2] = make_float4(scale * e2.x, scale * e2.y, scale * e2.z, scale * e2.w);
    op[3] = make_float4(scale * e3.x, scale * e3.y, scale * e3.z, scale * e3.w);
  }
}

extern "C" void kernel_launch(void* const* d_in, const int* in_sizes, int n_in,
                              void* d_out, int out_size) {
  const float* a = (const float*)d_in[0];
  const float* b = (const float*)d_in[1];
  float*       o = (float*)d_out;
  int nrows = in_sizes[0] / 1024;            // (B,4,256) -> B rows of 1024
  int threads = 256;                          // 16 rows per block
  int blocks = (nrows * 16 + threads - 1) / threads;
  neural_alu_kernel<<<blocks, threads>>>(a, b, o, nrows);
}

// round 10
// speedup vs baseline: 1.1241x; 1.1241x over previous
#include <cuda_runtime.h>

#define FULLMASK 0xffffffffu

// P1 helper: one 256-float block = 16 rows x 16 cols, lane l holds row l.
//   hs = row-l sum (lane-local);  ls = col-l sum via butterfly reduce-scatter.
__device__ __forceinline__ void load_sums(const float* __restrict__ p, int l,
                                          float& hs, float& ls) {
  const float4* p4 = reinterpret_cast<const float4*>(p) + 4 * l;
  float4 x0 = p4[0], x1 = p4[1], x2 = p4[2], x3 = p4[3];
  float u[16] = {x0.x, x0.y, x0.z, x0.w, x1.x, x1.y, x1.z, x1.w,
                 x2.x, x2.y, x2.z, x2.w, x3.x, x3.y, x3.z, x3.w};
  hs = ((u[0] + u[1]) + (u[2] + u[3])) + ((u[4] + u[5]) + (u[6] + u[7])) +
       ((u[8] + u[9]) + (u[10] + u[11])) + ((u[12] + u[13]) + (u[14] + u[15]));

  bool b8 = (l & 8) != 0;
  float w[8];
#pragma unroll
  for (int k = 0; k < 8; k++) {
    float send = b8 ? u[k] : u[k + 8];
    float keep = b8 ? u[k + 8] : u[k];
    w[k] = keep + __shfl_xor_sync(FULLMASK, send, 8, 16);
  }
  bool b4 = (l & 4) != 0;
  float x[4];
#pragma unroll
  for (int k = 0; k < 4; k++) {
    float send = b4 ? w[k] : w[k + 4];
    float keep = b4 ? w[k + 4] : w[k];
    x[k] = keep + __shfl_xor_sync(FULLMASK, send, 4, 16);
  }
  bool b2 = (l & 2) != 0;
  float y[2];
#pragma unroll
  for (int k = 0; k < 2; k++) {
    float send = b2 ? x[k] : x[k + 2];
    float keep = b2 ? x[k + 2] : x[k];
    y[k] = keep + __shfl_xor_sync(FULLMASK, send, 2, 16);
  }
  bool b1 = (l & 1) != 0;
  float send = b1 ? y[0] : y[1];
  float keep = b1 ? y[1] : y[0];
  ls = keep + __shfl_xor_sync(FULLMASK, send, 1, 16);
}

// Warp = 2 rows. Nibble-add id k = h*8 + byte*2 + (0:low,1:high), k in [0,16).
// Vector stride 20 floats: 16B-aligned for LDS.128/STS.128, 2-way bank spread.
__global__ __launch_bounds__(256, 4) void neural_alu_kernel(
    const float* __restrict__ A, const float* __restrict__ B,
    float* __restrict__ O, int nrows) {
  __shared__ __align__(16) float s_nx[8][16][20];  // "a" operand nibble vecs
  __shared__ __align__(16) float s_ny[8][16][20];  // "b" operand nibble vecs
  __shared__ __align__(16) float s_ev[8][16][20];  // [0:16)=el unnorm, [16]=1/Z
  __shared__ float s_c01[8][16][2];

  int tid  = threadIdx.x;
  int warp = tid >> 5;
  int lane = tid & 31;
  int h    = (tid >> 4) & 1;  // row within warp
  int l    = tid & 15;
  int row  = (blockIdx.x * 8 + warp) * 2 + h;
  if (row >= nrows) row = nrows - 1;  // exact grids never hit; keeps syncs safe

  const float* a = A + (size_t)row * 1024;
  const float* b = B + (size_t)row * 1024;

  // ---- P1: loads + row/col sums, publish nibble vectors --------------------
#pragma unroll
  for (int i = 0; i < 4; i++) {
    float ah, al, bh, bl;
    load_sums(a + i * 256, l, ah, al);
    load_sums(b + i * 256, l, bh, bl);
    int kL = h * 8 + i * 2;
    s_nx[warp][kL][l]     = al;
    s_nx[warp][kL + 1][l] = ah;
    s_ny[warp][kL][l]     = bl;
    s_ny[warp][kL + 1][l] = bh;
  }
  __syncwarp();

  // ---- P2: one lane = one complete nibble-add (lanes 16-31 idle) -----------
  int k = lane;
  float qs[16];
  float inv_ = 0.f;
  if (k < 16) {
    const float4* y4 = reinterpret_cast<const float4*>(s_ny[warp][k]);
    float4 t0 = y4[0], t1 = y4[1], t2 = y4[2], t3 = y4[3];
    float ey[16] = {t0.x, t0.y, t0.z, t0.w, t1.x, t1.y, t1.z, t1.w,
                    t2.x, t2.y, t2.z, t2.w, t3.x, t3.y, t3.z, t3.w};
    float my = ey[0];
#pragma unroll
    for (int s = 1; s < 16; s++) my = fmaxf(my, ey[s]);
    float Zy = 0.f;
#pragma unroll
    for (int s = 0; s < 16; s++) { ey[s] = __expf(100.f * (ey[s] - my)); Zy += ey[s]; }

    const float4* x4 = reinterpret_cast<const float4*>(s_nx[warp][k]);
    float4 m0 = x4[0], m1 = x4[1], m2 = x4[2], m3 = x4[3];
    float mx = fmaxf(fmaxf(fmaxf(m0.x, m0.y), fmaxf(m0.z, m0.w)),
               fmaxf(fmaxf(fmaxf(m1.x, m1.y), fmaxf(m1.z, m1.w)),
               fmaxf(fmaxf(fmaxf(m2.x, m2.y), fmaxf(m2.z, m2.w)),
                     fmaxf(fmaxf(m3.x, m3.y), fmaxf(m3.z, m3.w)))));

#pragma unroll
    for (int s = 0; s < 16; s++) qs[s] = 0.f;
    float Zx = 0.f, qhiT = 0.f;
#pragma unroll
    for (int c = 0; c < 4; c++) {
      float4 xc = x4[c];  // reload per chunk to cap register pressure
      float xr[4] = {xc.x, xc.y, xc.z, xc.w};
#pragma unroll
      for (int j = 0; j < 4; j++) {
        const int Ai = 4 * c + j;
        float e = __expf(100.f * (xr[j] - mx));
        Zx += e;
#pragma unroll
        for (int s = 0; s < 16; s++) {
          float prod = e * ey[(s - Ai) & 15];
          qs[s] += prod;
          if (Ai > s) qhiT += prod;  // wrapped pairs: exactly A+B>15
        }
      }
    }
    inv_ = 1.0f / (Zx * Zy);
    float c0 = qhiT * inv_;                 // P(A+B > 15)
    float c1 = fmaf(qs[15], inv_, c0);      // qs[15] == q[15] (no wrap at s=15)
    s_c01[warp][k][0] = c0;
    s_c01[warp][k][1] = c1;
  }
  __syncwarp();

  // ---- Carry chain (each adder lane replays its row's 8-step recurrence) ---
  if (k < 16) {
    int r = k >> 3;
    float pcs = 0.f, u1 = 0.f;
#pragma unroll
    for (int j = 0; j < 8; j++) {
      float pc = 1.f / (1.f + __expf(fmaf(-200.f, u1, 100.f)));
      float c0 = s_c01[warp][r * 8 + j][0];
      float c1 = s_c01[warp][r * 8 + j][1];
      if (j == (k & 7)) pcs = pc;
      u1 = fmaf(c1 - c0, pc, c0);
    }
    // sl[s] = (qs[s] + (qs[s-1]-qs[s])*pc) * inv ; el = exp(100*sl - 50)
    float Zl = 0.f;
#pragma unroll
    for (int s = 0; s < 16; s++) {
      float s0 = qs[s];
      float s1 = qs[(s + 15) & 15];
      float sv = fmaf(s1 - s0, pcs, s0) * inv_;
      float e  = __expf(fmaf(100.f, sv, -50.f));
      Zl += e;
      s_ev[warp][k][s] = e;
    }
    s_ev[warp][k][16] = 1.0f / Zl;
  }
  __syncwarp();

  // ---- P3: outer product output, 16 lanes/row, fully coalesced stores ------
  float* o = O + (size_t)row * 1024;
#pragma unroll
  for (int i = 0; i < 4; i++) {
    int kL = h * 8 + i * 2, kH = kL + 1;
    // scale = (eh[l]/Zh) * (1/Zl); out[16l+m] = scale * el[m]
    float scale = (s_ev[warp][kH][l] * s_ev[warp][kH][16]) * s_ev[warp][kL][16];
    const float4* e4 = reinterpret_cast<const float4*>(s_ev[warp][kL]);
    float4 e0 = e4[0], e1 = e4[1], e2 = e4[2], e3 = e4[3];
    float4* op = reinterpret_cast<float4*>(o + i * 256) + 4 * l;
    op[0] = make_float4(scale * e0.x, scale * e0.y, scale * e0.z, scale * e0.w);
    op[1] = make_float4(scale * e1.x, scale * e1.y, scale * e1.z, scale * e1.w);
    op[2] = make_float4(scale * e2.x, scale * e2.y, scale * e2.z, scale * e2.w);
    op[3] = make_float4(scale * e3.x, scale * e3.y, scale * e3.z, scale * e3.w);
  }
}

extern "C" void kernel_launch(void* const* d_in, const int* in_sizes, int n_in,
                              void* d_out, int out_size) {
  const float* a = (const float*)d_in[0];
  const float* b = (const float*)d_in[1];
  float*       o = (float*)d_out;
  int nrows = in_sizes[0] / 1024;            // (B,4,256) -> B rows of 1024
  int threads = 256;                          // 8 warps x 2 rows = 16 rows/block
  int blocks = (nrows * 16 + threads - 1) / threads;
  neural_alu_kernel<<<blocks, threads>>>(a, b, o, nrows);
}

// round 14
// speedup vs baseline: 1.1496x; 1.0227x over previous
#include <cuda_runtime.h>

#define FULLMASK 0xffffffffu

// P1 helper: one 256-float block = 16 rows x 16 cols, lane l holds row l.
//   hs = row-l sum (lane-local);  ls = col-l sum via butterfly reduce-scatter.
__device__ __forceinline__ void load_sums(const float* __restrict__ p, int l,
                                          float& hs, float& ls) {
  const float4* p4 = reinterpret_cast<const float4*>(p) + 4 * l;
  float4 x0 = p4[0], x1 = p4[1], x2 = p4[2], x3 = p4[3];
  float u[16] = {x0.x, x0.y, x0.z, x0.w, x1.x, x1.y, x1.z, x1.w,
                 x2.x, x2.y, x2.z, x2.w, x3.x, x3.y, x3.z, x3.w};
  hs = ((u[0] + u[1]) + (u[2] + u[3])) + ((u[4] + u[5]) + (u[6] + u[7])) +
       ((u[8] + u[9]) + (u[10] + u[11])) + ((u[12] + u[13]) + (u[14] + u[15]));

  bool b8 = (l & 8) != 0;
  float w[8];
#pragma unroll
  for (int k = 0; k < 8; k++) {
    float send = b8 ? u[k] : u[k + 8];
    float keep = b8 ? u[k + 8] : u[k];
    w[k] = keep + __shfl_xor_sync(FULLMASK, send, 8, 16);
  }
  bool b4 = (l & 4) != 0;
  float x[4];
#pragma unroll
  for (int k = 0; k < 4; k++) {
    float send = b4 ? w[k] : w[k + 4];
    float keep = b4 ? w[k + 4] : w[k];
    x[k] = keep + __shfl_xor_sync(FULLMASK, send, 4, 16);
  }
  bool b2 = (l & 2) != 0;
  float y[2];
#pragma unroll
  for (int k = 0; k < 2; k++) {
    float send = b2 ? x[k] : x[k + 2];
    float keep = b2 ? x[k + 2] : x[k];
    y[k] = keep + __shfl_xor_sync(FULLMASK, send, 2, 16);
  }
  bool b1 = (l & 1) != 0;
  float send = b1 ? y[0] : y[1];
  float keep = b1 ? y[1] : y[0];
  ls = keep + __shfl_xor_sync(FULLMASK, send, 1, 16);
}

// Warp = 4 rows = 32 nibble-adds, one per lane (P2/carry run full-width).
// Nibble-add id k: row-in-warp = k>>3, byte = (k>>1)&3, nib = k&1 (0=lo,1=hi).
// Vector stride 20 floats: 16B-aligned for LDS.128/STS.128, spreads banks.
__global__ __launch_bounds__(256, 4) void neural_alu_kernel(
    const float* __restrict__ A, const float* __restrict__ B,
    float* __restrict__ O, int nrows) {
  __shared__ __align__(16) float s_x[8][32][20];  // "a" nibble vecs; later el
  __shared__ __align__(16) float s_y[8][32][20];  // "b" nibble vecs
  __shared__ float s_c01[8][32][2];

  int tid  = threadIdx.x;
  int warp = tid >> 5;
  int lane = tid & 31;
  int h    = (lane >> 4) & 1;  // row within a row-pair
  int l    = lane & 15;
  int rowbase = (blockIdx.x * 8 + warp) * 4;

  // ---- P1: loads + row/col sums for 4 rows, publish 32 nibble vectors ------
#pragma unroll
  for (int rp = 0; rp < 2; rp++) {
    int row = rowbase + rp * 2 + h;
    if (row >= nrows) row = nrows - 1;  // never hit for exact grids
    const float* a = A + (size_t)row * 1024;
    const float* b = B + (size_t)row * 1024;
#pragma unroll
    for (int i = 0; i < 4; i++) {
      float ah, al, bl, bh;
      load_sums(a + i * 256, l, ah, al);
      load_sums(b + i * 256, l, bh, bl);
      int kL = rp * 16 + h * 8 + i * 2;
      s_x[warp][kL][l]     = al;
      s_x[warp][kL + 1][l] = ah;
      s_y[warp][kL][l]     = bl;
      s_y[warp][kL + 1][l] = bh;
    }
  }
  __syncwarp();

  // ---- P2: lane k = one complete nibble-add (all 32 lanes active) ----------
  int k = lane;
  float qs[16];
  float inv_;
  {
    const float4* y4 = reinterpret_cast<const float4*>(s_y[warp][k]);
    float4 t0 = y4[0], t1 = y4[1], t2 = y4[2], t3 = y4[3];
    float ey[16] = {t0.x, t0.y, t0.z, t0.w, t1.x, t1.y, t1.z, t1.w,
                    t2.x, t2.y, t2.z, t2.w, t3.x, t3.y, t3.z, t3.w};
    float my = ey[0];
#pragma unroll
    for (int s = 1; s < 16; s++) my = fmaxf(my, ey[s]);
    float Zy = 0.f;
#pragma unroll
    for (int s = 0; s < 16; s++) { ey[s] = __expf(100.f * (ey[s] - my)); Zy += ey[s]; }

    const float4* x4 = reinterpret_cast<const float4*>(s_x[warp][k]);
    float4 m0 = x4[0], m1 = x4[1], m2 = x4[2], m3 = x4[3];
    float mx = fmaxf(fmaxf(fmaxf(m0.x, m0.y), fmaxf(m0.z, m0.w)),
               fmaxf(fmaxf(fmaxf(m1.x, m1.y), fmaxf(m1.z, m1.w)),
               fmaxf(fmaxf(fmaxf(m2.x, m2.y), fmaxf(m2.z, m2.w)),
                     fmaxf(fmaxf(m3.x, m3.y), fmaxf(m3.z, m3.w)))));

#pragma unroll
    for (int s = 0; s < 16; s++) qs[s] = 0.f;
    float Zx = 0.f, qhiT = 0.f;
#pragma unroll
    for (int c = 0; c < 4; c++) {
      float4 xc = x4[c];  // reload per chunk to cap register pressure
      float xr[4] = {xc.x, xc.y, xc.z, xc.w};
#pragma unroll
      for (int j = 0; j < 4; j++) {
        const int Ai = 4 * c + j;
        float e = __expf(100.f * (xr[j] - mx));
        Zx += e;
#pragma unroll
        for (int s = 0; s < 16; s++) {
          float prod = e * ey[(s - Ai) & 15];
          qs[s] += prod;
          if (Ai > s) qhiT += prod;  // wrapped pairs: exactly A+B>15
        }
      }
    }
    inv_ = 1.0f / (Zx * Zy);
    float c0 = qhiT * inv_;                 // P(A+B > 15)
    float c1 = fmaf(qs[15], inv_, c0);      // qs[15] == q[15] (no wrap at s=15)
    s_c01[warp][k][0] = c0;
    s_c01[warp][k][1] = c1;
  }
  __syncwarp();

  // ---- Carry chain: each lane replays its row's 8-step recurrence ----------
  // Then writes its output-softmax numerators. s_x is reused: lane k has
  // finished all reads of s_x[k]; cross-lane reads happen after __syncwarp.
  {
    int r = k >> 3;
    float pcs = 0.f, u1 = 0.f;
#pragma unroll
    for (int j = 0; j < 8; j++) {
      float pc = 1.f / (1.f + __expf(fmaf(-200.f, u1, 100.f)));
      float c0 = s_c01[warp][r * 8 + j][0];
      float c1 = s_c01[warp][r * 8 + j][1];
      if (j == (k & 7)) pcs = pc;
      u1 = fmaf(c1 - c0, pc, c0);
    }
    // sv[s] = (qs[s] + (qs[s-1]-qs[s])*pc) * inv ; e = exp(100*sv - 50)
    float Zl = 0.f;
#pragma unroll
    for (int s = 0; s < 16; s++) {
      float s0 = qs[s];
      float s1 = qs[(s + 15) & 15];
      float sv = fmaf(s1 - s0, pcs, s0) * inv_;
      float e  = __expf(fmaf(100.f, sv, -50.f));
      Zl += e;
      s_x[warp][k][s] = e;
    }
    s_x[warp][k][16] = 1.0f / Zl;
  }
  __syncwarp();

  // ---- P3: outer-product output for 4 rows, fully coalesced STG.128 --------
#pragma unroll
  for (int rp = 0; rp < 2; rp++) {
    int row = rowbase + rp * 2 + h;
    if (row >= nrows) row = nrows - 1;
    float* o = O + (size_t)row * 1024;
#pragma unroll
    for (int i = 0; i < 4; i++) {
      int kL = rp * 16 + h * 8 + i * 2, kH = kL + 1;
      // scale = (eh[l]/Zh) * (1/Zl); out[16l+m] = scale * el[m]
      float scale = (s_x[warp][kH][l] * s_x[warp][kH][16]) * s_x[warp][kL][16];
      const float4* e4 = reinterpret_cast<const float4*>(s_x[warp][kL]);
      float4 e0 = e4[0], e1 = e4[1], e2 = e4[2], e3 = e4[3];
      float4* op = reinterpret_cast<float4*>(o + i * 256) + 4 * l;
      op[0] = make_float4(scale * e0.x, scale * e0.y, scale * e0.z, scale * e0.w);
      op[1] = make_float4(scale * e1.x, scale * e1.y, scale * e1.z, scale * e1.w);
      op[2] = make_float4(scale * e2.x, scale * e2.y, scale * e2.z, scale * e2.w);
      op[3] = make_float4(scale * e3.x, scale * e3.y, scale * e3.z, scale * e3.w);
    }
  }
}

extern "C" void kernel_launch(void* const* d_in, const int* in_sizes, int n_in,
                              void* d_out, int out_size) {
  const float* a = (const float*)d_in[0];
  const float* b = (const float*)d_in[1];
  float*       o = (float*)d_out;
  int nrows = in_sizes[0] / 1024;            // (B,4,256) -> B rows of 1024
  int rows_per_block = 32;                    // 8 warps x 4 rows
  int blocks = (nrows + rows_per_block - 1) / rows_per_block;
  neural_alu_kernel<<<blocks, 256>>>(a, b, o, nrows);
}